// round 12
// baseline (speedup 1.0000x reference)
#include <cuda_runtime.h>
#include <cuda_bf16.h>

#define TSTEPS 10
#define NCH 96
#define NEG_INF (-1e30f)
#define NW 16            // warps per CTA
#define RPW 8            // rows per warp (NW*RPW = 128)

// Pairwise named barrier: both warps of a pair call with the same id, 64 threads.
__device__ __forceinline__ void bar_pair(int id) {
    asm volatile("bar.sync %0, 64;" :: "r"(id) : "memory");
}

// Row-max over a float4: 7 FMNMX (2 predicated) + 2 SHFL (round-6 form).
__device__ __forceinline__ float4 rowmax4(float4 v, int tx) {
    const unsigned mask = 0xffffffffu;
    float left  = __shfl_up_sync(mask, v.w, 1);   // garbage in lane 0 (predicated off)
    float right = __shfl_down_sync(mask, v.x, 1); // garbage in lane 31 (predicated off)
    float t01 = fmaxf(v.x, v.y);
    float t12 = fmaxf(v.y, v.z);
    float t23 = fmaxf(v.z, v.w);
    float4 rm;
    rm.x = t01;
    if (tx > 0)  rm.x = fmaxf(t01, left);    // @P FMNMX
    rm.y = fmaxf(t01, v.z);
    rm.z = fmaxf(t12, v.w);
    rm.w = t23;
    if (tx < 31) rm.w = fmaxf(t23, right);   // @P FMNMX
    return rm;
}

// v = v + p*(m - v) as fma2(p, m, fma2(-p, v, v)) on packed f32x2 (round-6 form).
__device__ __forceinline__ void blend4(float4& v, float4 m,
                                       unsigned long long pp,
                                       unsigned long long np) {
    asm("{\n\t"
        ".reg .b64 vv, mm, cc;\n\t"
        "mov.b64 vv, {%0, %1};\n\t"
        "mov.b64 mm, {%4, %5};\n\t"
        "fma.rn.f32x2 cc, %8, vv, vv;\n\t"
        "fma.rn.f32x2 cc, %9, mm, cc;\n\t"
        "mov.b64 {%0, %1}, cc;\n\t"
        "mov.b64 vv, {%2, %3};\n\t"
        "mov.b64 mm, {%6, %7};\n\t"
        "fma.rn.f32x2 cc, %8, vv, vv;\n\t"
        "fma.rn.f32x2 cc, %9, mm, cc;\n\t"
        "mov.b64 {%2, %3}, cc;\n\t"
        "}"
        : "+f"(v.x), "+f"(v.y), "+f"(v.z), "+f"(v.w)
        : "f"(m.x), "f"(m.y), "f"(m.z), "f"(m.w),
          "l"(np), "l"(pp));
}

__device__ __forceinline__ unsigned long long pack2(float a, float b) {
    unsigned long long r;
    asm("mov.b64 %0, {%1, %2};" : "=l"(r) : "f"(a), "f"(b));
    return r;
}

// EXACT round-6 kernel with one change: the two pairwise barriers are
// ordered by ODD/EVEN pair id instead of ascending id. Odd-id pairs
// {1,3,..,15} are warp-disjoint and complete in one parallel round; even-id
// pairs {2,4,..,14} likewise. This removes the 16-warp release wavefront
// that ascending order created (warp wy couldn't arrive at pair wy+1 until
// pair wy released, chaining all warps each step). Deadlock-free: global
// order = odd class then even class; every warp has at most one pair in
// each class. Halo reads are still each protected by their own pair.
extern "C" __global__ void __launch_bounds__(512, 2)
cpool_kernel(const float* __restrict__ x,
             const float* __restrict__ ps,
             float* __restrict__ out) {
    __shared__ float4 halo[2][NW][2][32];     // 32KB

    const int img = blockIdx.x;               // b*96 + c
    const float p = __ldg(ps + img % NCH);
    const unsigned long long pp = pack2(p, p);
    const unsigned long long np = pack2(-p, -p);

    const int tx = threadIdx.x;               // 0..31
    const int wy = threadIdx.y;               // 0..15
    const int r0 = wy * RPW;

    // ---- Load own 8 rows straight into registers (coalesced LDG.128) ----
    const float4* X4 = (const float4*)(x + (size_t)img * 128 * 128);
    float4 v[RPW];
    #pragma unroll
    for (int k = 0; k < RPW; k++)
        v[k] = X4[(r0 + k) * 32 + tx];

    const float4 ninf = make_float4(NEG_INF, NEG_INF, NEG_INF, NEG_INF);

    #pragma unroll 1
    for (int t = 0; t < TSTEPS; t++) {
        const int b = t & 1;

        // Phase 1: publish pre-update row-maxes of boundary rows.
        float4 rm_first = rowmax4(v[0], tx);
        float4 rm_last  = rowmax4(v[RPW - 1], tx);
        halo[b][wy][0][tx] = rm_first;
        halo[b][wy][1][tx] = rm_last;

        // Pairwise sync, odd-id pairs first, then even-id pairs.
        // Warp wy belongs to pair wy (with wy-1) and pair wy+1 (with wy+1);
        // the two ids are consecutive, so exactly one is odd.
        if (wy & 1) {
            bar_pair(wy);                     // odd id
            if (wy < NW - 1) bar_pair(wy + 1);// even id
        } else {
            if (wy < NW - 1) bar_pair(wy + 1);// odd id
            if (wy > 0)      bar_pair(wy);    // even id
        }

        // Phase 2: fetch neighbor halo row-maxes.
        float4 rm_prev  = (wy > 0)      ? halo[b][wy - 1][1][tx] : ninf;
        float4 rm_below = (wy < NW - 1) ? halo[b][wy + 1][0][tx] : ninf;

        // Phase 3: register sliding window, in-place (rm_* are pre-update).
        float4 rm_cur = rm_first;
        #pragma unroll
        for (int k = 0; k < RPW; k++) {
            float4 rm_next;
            if (k == RPW - 1)      rm_next = rm_below;
            else if (k == RPW - 2) rm_next = rm_last;
            else                   rm_next = rowmax4(v[k + 1], tx);

            float4 m;
            m.x = fmaxf(fmaxf(rm_prev.x, rm_cur.x), rm_next.x);
            m.y = fmaxf(fmaxf(rm_prev.y, rm_cur.y), rm_next.y);
            m.z = fmaxf(fmaxf(rm_prev.z, rm_cur.z), rm_next.z);
            m.w = fmaxf(fmaxf(rm_prev.w, rm_cur.w), rm_next.w);
            blend4(v[k], m, pp, np);

            rm_prev = rm_cur;
            rm_cur  = rm_next;
        }
        // Double-buffered halo: no second barrier needed.
    }

    // ---- 2x2 avgpool stride 2 straight from registers -> 64x64 ----
    float* o_img = out + (size_t)img * 64 * 64;
    #pragma unroll
    for (int oy = 0; oy < RPW / 2; oy++) {
        float4 a = v[2 * oy];
        float4 b = v[2 * oy + 1];
        float2 r;
        r.x = 0.25f * ((a.x + a.y) + (b.x + b.y));
        r.y = 0.25f * ((a.z + a.w) + (b.z + b.w));
        *(float2*)(o_img + (4 * wy + oy) * 64 + 2 * tx) = r;
    }
}

extern "C" void kernel_launch(void* const* d_in, const int* in_sizes, int n_in,
                              void* d_out, int out_size) {
    const float* x  = (const float*)d_in[0];
    const float* ps = (const float*)d_in[1];
    if (n_in >= 2 && in_sizes[0] == NCH) {   // defensive input-order check
        const float* tmp = x; x = ps; ps = tmp;
    }

    dim3 grid(32 * NCH);        // 3072 images
    dim3 block(32, NW);         // 512 threads, warp = one image row
    cpool_kernel<<<grid, block>>>(x, ps, (float*)d_out);
}

// round 13
// speedup vs baseline: 1.1919x; 1.1919x over previous
#include <cuda_runtime.h>
#include <cuda_bf16.h>

#define TSTEPS 10
#define NCH 96
#define NEG_INF (-1e30f)
#define NW 16            // warps per CTA
#define RPW 8            // rows per warp (NW*RPW = 128)

// Pairwise named barrier: both warps of a pair call with the same id, 64 threads.
__device__ __forceinline__ void bar_pair(int id) {
    asm volatile("bar.sync %0, 64;" :: "r"(id) : "memory");
}

// Row-max over a float4: 7 FMNMX (2 predicated) + 2 SHFL.
__device__ __forceinline__ float4 rowmax4(float4 v, int tx) {
    const unsigned mask = 0xffffffffu;
    float left  = __shfl_up_sync(mask, v.w, 1);   // garbage in lane 0 (predicated off)
    float right = __shfl_down_sync(mask, v.x, 1); // garbage in lane 31 (predicated off)
    float t01 = fmaxf(v.x, v.y);
    float t12 = fmaxf(v.y, v.z);
    float t23 = fmaxf(v.z, v.w);
    float4 rm;
    rm.x = t01;
    if (tx > 0)  rm.x = fmaxf(t01, left);    // @P FMNMX
    rm.y = fmaxf(t01, v.z);
    rm.z = fmaxf(t12, v.w);
    rm.w = t23;
    if (tx < 31) rm.w = fmaxf(t23, right);   // @P FMNMX
    return rm;
}

// v = v + p*(m - v) as fma2(p, m, fma2(-p, v, v)) on packed f32x2.
__device__ __forceinline__ void blend4(float4& v, float4 m,
                                       unsigned long long pp,
                                       unsigned long long np) {
    asm("{\n\t"
        ".reg .b64 vv, mm, cc;\n\t"
        "mov.b64 vv, {%0, %1};\n\t"
        "mov.b64 mm, {%4, %5};\n\t"
        "fma.rn.f32x2 cc, %8, vv, vv;\n\t"
        "fma.rn.f32x2 cc, %9, mm, cc;\n\t"
        "mov.b64 {%0, %1}, cc;\n\t"
        "mov.b64 vv, {%2, %3};\n\t"
        "mov.b64 mm, {%6, %7};\n\t"
        "fma.rn.f32x2 cc, %8, vv, vv;\n\t"
        "fma.rn.f32x2 cc, %9, mm, cc;\n\t"
        "mov.b64 {%2, %3}, cc;\n\t"
        "}"
        : "+f"(v.x), "+f"(v.y), "+f"(v.z), "+f"(v.w)
        : "f"(m.x), "f"(m.y), "f"(m.z), "f"(m.w),
          "l"(np), "l"(pp));
}

__device__ __forceinline__ unsigned long long pack2(float a, float b) {
    unsigned long long r;
    asm("mov.b64 %0, {%1, %2};" : "=l"(r) : "f"(a), "f"(b));
    return r;
}

// One CTA per (batch, channel) image. Each warp holds its 8 rows in
// registers for all 10 timesteps. Halo row-maxes go through double-buffered
// SMEM, synchronized by PAIRWISE named barriers between adjacent warps only
// (no full-CTA barrier, no convoy). Warp wy syncs barrier id=wy (with warp
// above) then id=wy+1 (with warp below); ascending order -> deadlock-free.
// Double buffer: conflicting halo reuse between neighbors is separated by
// two pairwise syncs, so pre-update values are always read.
extern "C" __global__ void __launch_bounds__(512, 2)
cpool_kernel(const float* __restrict__ x,
             const float* __restrict__ ps,
             float* __restrict__ out) {
    __shared__ float4 halo[2][NW][2][32];     // 32KB

    const int img = blockIdx.x;               // b*96 + c
    const float p = ps[img % NCH];
    const unsigned long long pp = pack2(p, p);
    const unsigned long long np = pack2(-p, -p);

    const int tx = threadIdx.x;               // 0..31
    const int wy = threadIdx.y;               // 0..15
    const int r0 = wy * RPW;

    // ---- Load own 8 rows straight into registers (coalesced LDG.128) ----
    const float4* X4 = (const float4*)(x + (size_t)img * 128 * 128);
    float4 v[RPW];
    #pragma unroll
    for (int k = 0; k < RPW; k++)
        v[k] = X4[(r0 + k) * 32 + tx];

    const float4 ninf = make_float4(NEG_INF, NEG_INF, NEG_INF, NEG_INF);

    #pragma unroll 1
    for (int t = 0; t < TSTEPS; t++) {
        const int b = t & 1;

        // Phase 1: publish pre-update row-maxes of boundary rows.
        float4 rm_first = rowmax4(v[0], tx);
        float4 rm_last  = rowmax4(v[RPW - 1], tx);
        halo[b][wy][0][tx] = rm_first;
        halo[b][wy][1][tx] = rm_last;

        // Pairwise sync with the two neighbor warps (ascending barrier ids).
        if (wy > 0)      bar_pair(wy);        // with warp wy-1
        if (wy < NW - 1) bar_pair(wy + 1);    // with warp wy+1

        // Phase 2: fetch neighbor halo row-maxes.
        float4 rm_prev  = (wy > 0)      ? halo[b][wy - 1][1][tx] : ninf;
        float4 rm_below = (wy < NW - 1) ? halo[b][wy + 1][0][tx] : ninf;

        // Phase 3: register sliding window, in-place (rm_* are pre-update).
        float4 rm_cur = rm_first;
        #pragma unroll
        for (int k = 0; k < RPW; k++) {
            float4 rm_next;
            if (k == RPW - 1)      rm_next = rm_below;
            else if (k == RPW - 2) rm_next = rm_last;
            else                   rm_next = rowmax4(v[k + 1], tx);

            float4 m;
            m.x = fmaxf(fmaxf(rm_prev.x, rm_cur.x), rm_next.x);
            m.y = fmaxf(fmaxf(rm_prev.y, rm_cur.y), rm_next.y);
            m.z = fmaxf(fmaxf(rm_prev.z, rm_cur.z), rm_next.z);
            m.w = fmaxf(fmaxf(rm_prev.w, rm_cur.w), rm_next.w);
            blend4(v[k], m, pp, np);

            rm_prev = rm_cur;
            rm_cur  = rm_next;
        }
    }

    // ---- 2x2 avgpool stride 2 straight from registers -> 64x64 ----
    float* o_img = out + (size_t)img * 64 * 64;
    #pragma unroll
    for (int oy = 0; oy < RPW / 2; oy++) {
        float4 a = v[2 * oy];
        float4 b = v[2 * oy + 1];
        float2 r;
        r.x = 0.25f * ((a.x + a.y) + (b.x + b.y));
        r.y = 0.25f * ((a.z + a.w) + (b.z + b.w));
        *(float2*)(o_img + (4 * wy + oy) * 64 + 2 * tx) = r;
    }
}

extern "C" void kernel_launch(void* const* d_in, const int* in_sizes, int n_in,
                              void* d_out, int out_size) {
    const float* x  = (const float*)d_in[0];
    const float* ps = (const float*)d_in[1];
    if (n_in >= 2 && in_sizes[0] == NCH) {   // defensive input-order check
        const float* tmp = x; x = ps; ps = tmp;
    }

    dim3 grid(32 * NCH);        // 3072 images
    dim3 block(32, NW);         // 512 threads, warp = one image row
    cpool_kernel<<<grid, block>>>(x, ps, (float*)d_out);
}